// round 2
// baseline (speedup 1.0000x reference)
#include <cuda_runtime.h>
#include <math.h>

#define N0C 200000
#define N1C 160000
#define N2C 100000

// ---------------- scratch (static device arrays; no allocation) -------------
__device__ __align__(16) float g_X [N2C * 64];   // 6.4M floats (covers N1*32 too)
__device__ __align__(16) float g_T0[N2C * 64];
__device__ __align__(16) float g_T1[N2C * 64];
__device__ double g_part[2 * 256 * 64];          // BN partials: [sum | sumsq]
__device__ float  g_scale[64];
__device__ float  g_shift[64];

// ---------------- conv1: 125 taps, Cin=1 -> Cout=32, fused relu -------------
__global__ __launch_bounds__(256) void conv1_kernel(
    const float* __restrict__ feats, const int* __restrict__ nbr,
    const float* __restrict__ W, float* __restrict__ out,
    int Nout, int Nin, int taps)
{
    __shared__ float4 Ws[125 * 8];   // (taps, 32) as float4 x8 per tap
    for (int i = threadIdx.x; i < taps * 8; i += 256)
        Ws[i] = reinterpret_cast<const float4*>(W)[i];
    __syncthreads();

    int j = blockIdx.x * 256 + threadIdx.x;
    if (j >= Nout) return;

    float acc[32];
#pragma unroll
    for (int c = 0; c < 32; c++) acc[c] = 0.f;

    for (int k = 0; k < taps; k++) {
        int idx = nbr[k * Nout + j];
        if (idx < Nin) {
            float v = feats[idx];
#pragma unroll
            for (int q = 0; q < 8; q++) {
                float4 w = Ws[k * 8 + q];
                acc[4 * q + 0] += v * w.x;
                acc[4 * q + 1] += v * w.y;
                acc[4 * q + 2] += v * w.z;
                acc[4 * q + 3] += v * w.w;
            }
        }
    }
    float4* o = reinterpret_cast<float4*>(out + (size_t)j * 32);
#pragma unroll
    for (int q = 0; q < 8; q++)
        o[q] = make_float4(fmaxf(acc[4 * q + 0], 0.f), fmaxf(acc[4 * q + 1], 0.f),
                           fmaxf(acc[4 * q + 2], 0.f), fmaxf(acc[4 * q + 3], 0.f));
}

// ---------------- generic tiled gather-GEMM conv ----------------------------
// out[j, :] = sum_k X[nbr[k, j], :] @ W[k]   (nbr==Nin -> zero row)
// Tile: TM output rows per block, 256 threads.
// Thread (tcol = tid&7, trow = tid>>3) computes RPT rows x (COUT/8) cols,
// where RPT = TM/32.
template <int CIN, int COUT, int TM>
__global__ __launch_bounds__(256) void conv_kernel(
    const float* __restrict__ X, const int* __restrict__ nbr,
    const float* __restrict__ W, float* __restrict__ out,
    int Nout, int Nin, int taps)
{
    constexpr int AP  = CIN + 1;        // padded A stride (conflict-free column reads)
    constexpr int CPT = COUT / 8;       // cols per thread: 4 or 8
    constexpr int RPT = TM / 32;        // rows per thread: 4 (TM=128) or 2 (TM=64)
    constexpr int QPR = CIN / 4;        // float4 per row
    constexpr int STAGE_IT = TM * QPR / 256;
    constexpr int WIT = (CIN * COUT) / 1024;  // W float4 loads per thread

    __shared__ float As[TM * AP];
    __shared__ float Ws[CIN * COUT];

    const int tid  = threadIdx.x;
    const int tcol = tid & 7;
    const int trow = tid >> 3;          // 0..31
    const int row0 = blockIdx.x * TM;

    float acc[RPT][CPT];
#pragma unroll
    for (int i = 0; i < RPT; i++)
#pragma unroll
        for (int j = 0; j < CPT; j++) acc[i][j] = 0.f;

    for (int k = 0; k < taps; k++) {
        // stage weights for this tap
        const float4* Wk4 = reinterpret_cast<const float4*>(W + (size_t)k * CIN * COUT);
#pragma unroll
        for (int i = 0; i < WIT; i++)
            reinterpret_cast<float4*>(Ws)[tid + 256 * i] = Wk4[tid + 256 * i];

        // stage gathered A tile (row-contiguous float4 loads)
#pragma unroll
        for (int it = 0; it < STAGE_IT; it++) {
            int Q = tid + 256 * it;
            int r = Q / QPR;
            int q = Q - r * QPR;
            int grow = row0 + r;
            float4 v = make_float4(0.f, 0.f, 0.f, 0.f);
            if (grow < Nout) {
                int idx = nbr[k * Nout + grow];
                if (idx < Nin)
                    v = reinterpret_cast<const float4*>(X + (size_t)idx * CIN)[q];
            }
            float* a = As + r * AP + q * 4;
            a[0] = v.x; a[1] = v.y; a[2] = v.z; a[3] = v.w;
        }
        __syncthreads();

        // register-tiled accumulate
#pragma unroll 8
        for (int kk = 0; kk < CIN; kk++) {
            float a[RPT];
#pragma unroll
            for (int i = 0; i < RPT; i++)
                a[i] = As[(trow * RPT + i) * AP + kk];
#pragma unroll
            for (int j = 0; j < CPT / 4; j++) {
                float4 w = reinterpret_cast<const float4*>(Ws + kk * COUT)[tcol * (CPT / 4) + j];
#pragma unroll
                for (int i = 0; i < RPT; i++) {
                    acc[i][4 * j + 0] += a[i] * w.x;
                    acc[i][4 * j + 1] += a[i] * w.y;
                    acc[i][4 * j + 2] += a[i] * w.z;
                    acc[i][4 * j + 3] += a[i] * w.w;
                }
            }
        }
        __syncthreads();
    }

    // store raw conv output (BN applied later)
#pragma unroll
    for (int i = 0; i < RPT; i++) {
        int grow = row0 + trow * RPT + i;
        if (grow < Nout) {
            float4* o = reinterpret_cast<float4*>(out + (size_t)grow * COUT);
#pragma unroll
            for (int j = 0; j < CPT / 4; j++)
                o[tcol * (CPT / 4) + j] =
                    make_float4(acc[i][4 * j + 0], acc[i][4 * j + 1],
                                acc[i][4 * j + 2], acc[i][4 * j + 3]);
        }
    }
}

// ---------------- BN statistics: deterministic two-stage reduction ----------
template <int C>
__global__ __launch_bounds__(256) void reduce_kernel(const float* __restrict__ x, int N)
{
    constexpr int G = 256 / C;
    int c = threadIdx.x % C;
    int g = threadIdx.x / C;
    double s = 0.0, ss = 0.0;
    for (long r = (long)blockIdx.x * G + g; r < N; r += (long)gridDim.x * G) {
        double v = (double)x[r * C + c];
        s += v;
        ss += v * v;
    }
    __shared__ double sh[512];
    sh[threadIdx.x] = s;
    sh[256 + threadIdx.x] = ss;
    __syncthreads();
    if (g == 0) {
#pragma unroll
        for (int gg = 1; gg < G; gg++) {
            s  += sh[gg * C + c];
            ss += sh[256 + gg * C + c];
        }
        g_part[blockIdx.x * 64 + c] = s;
        g_part[16384 + blockIdx.x * 64 + c] = ss;
    }
}

template <int C>
__global__ void finalize_kernel(const float* __restrict__ gam,
                                const float* __restrict__ bet, double Ninv)
{
    int c = threadIdx.x;
    if (c < C) {
        double s = 0.0, ss = 0.0;
        for (int p = 0; p < 256; p++) {
            s  += g_part[p * 64 + c];
            ss += g_part[16384 + p * 64 + c];
        }
        double mu  = s * Ninv;
        double var = ss * Ninv - mu * mu;
        float  sc  = (float)((double)gam[c] / sqrt(var + 1e-5));
        g_scale[c] = sc;
        g_shift[c] = bet[c] - (float)mu * sc;
    }
}

// ---------------- elementwise BN apply ---------------------------------------
__global__ void ew_bn_relu_kernel(const float* __restrict__ x, float* __restrict__ y,
                                  int total, int cmask)
{
    int i = blockIdx.x * blockDim.x + threadIdx.x;
    if (i < total) {
        int c = i & cmask;
        y[i] = fmaxf(fmaf(x[i], g_scale[c], g_shift[c]), 0.f);
    }
}

__global__ void ew_bn_add_relu_kernel(const float* __restrict__ x,
                                      const float* __restrict__ res,
                                      float* __restrict__ y, int total, int cmask)
{
    int i = blockIdx.x * blockDim.x + threadIdx.x;
    if (i < total) {
        int c = i & cmask;
        y[i] = fmaxf(res[i] + fmaf(x[i], g_scale[c], g_shift[c]), 0.f);
    }
}

// ---------------- host orchestration -----------------------------------------
static void run_block32(const float* const* p, const int* nbr,
                        float* x, float* t0, float* t1)
{
    // p: wa, wb, g1, b1, g2, b2
    int tiles = (N1C + 127) / 128;
    int tot   = N1C * 32;
    conv_kernel<32, 32, 128><<<tiles, 256>>>(x, nbr, p[0], t0, N1C, N1C, 27);
    reduce_kernel<32><<<256, 256>>>(t0, N1C);
    finalize_kernel<32><<<1, 32>>>(p[2], p[3], 1.0 / N1C);
    ew_bn_relu_kernel<<<(tot + 255) / 256, 256>>>(t0, t1, tot, 31);
    conv_kernel<32, 32, 128><<<tiles, 256>>>(t1, nbr, p[1], t0, N1C, N1C, 27);
    reduce_kernel<32><<<256, 256>>>(t0, N1C);
    finalize_kernel<32><<<1, 32>>>(p[4], p[5], 1.0 / N1C);
    ew_bn_add_relu_kernel<<<(tot + 255) / 256, 256>>>(t0, x, x, tot, 31);
}

static void run_block64(const float* const* p, const int* nbr,
                        float* x, float* t0, float* scratch, float* dst)
{
    int tiles = (N2C + 63) / 64;
    int tot   = N2C * 64;
    conv_kernel<64, 64, 64><<<tiles, 256>>>(x, nbr, p[0], t0, N2C, N2C, 27);
    reduce_kernel<64><<<256, 256>>>(t0, N2C);
    finalize_kernel<64><<<1, 64>>>(p[2], p[3], 1.0 / N2C);
    ew_bn_relu_kernel<<<(tot + 255) / 256, 256>>>(t0, scratch, tot, 63);
    conv_kernel<64, 64, 64><<<tiles, 256>>>(scratch, nbr, p[1], t0, N2C, N2C, 27);
    reduce_kernel<64><<<256, 256>>>(t0, N2C);
    finalize_kernel<64><<<1, 64>>>(p[4], p[5], 1.0 / N2C);
    ew_bn_add_relu_kernel<<<(tot + 255) / 256, 256>>>(t0, x, dst, tot, 63);
}

extern "C" void kernel_launch(void* const* d_in, const int* in_sizes, int n_in,
                              void* d_out, int out_size)
{
    static float* pX  = nullptr;
    static float* pT0 = nullptr;
    static float* pT1 = nullptr;
    if (!pX) {
        cudaGetSymbolAddress((void**)&pX,  g_X);
        cudaGetSymbolAddress((void**)&pT0, g_T0);
        cudaGetSymbolAddress((void**)&pT1, g_T1);
    }

    const float* feats = (const float*)d_in[0];
    const float* W1    = (const float*)d_in[1];
    const float* W2    = (const float*)d_in[2];

    const int *nbr1, *nbr_e1, *nbr2, *nbr_e2;
    const float* blk[4][6];  // per block: wa, wb, g1, b1, g2, b2

    if (in_sizes[3] == 125 * N1C) {
        // dict insertion order: feats, W1, W2, nbr1, nbr_e1, nbr2, nbr_e2, blocks...
        nbr1   = (const int*)d_in[3];
        nbr_e1 = (const int*)d_in[4];
        nbr2   = (const int*)d_in[5];
        nbr_e2 = (const int*)d_in[6];
        for (int b = 0; b < 4; b++)
            for (int j = 0; j < 6; j++)
                blk[b][j] = (const float*)d_in[7 + b * 6 + j];
    } else {
        // reference signature order: feats, W1, W2, blocks..., nbr1, nbr_e1, nbr2, nbr_e2
        for (int b = 0; b < 4; b++)
            for (int j = 0; j < 6; j++)
                blk[b][j] = (const float*)d_in[3 + b * 6 + j];
        nbr1   = (const int*)d_in[27];
        nbr_e1 = (const int*)d_in[28];
        nbr2   = (const int*)d_in[29];
        nbr_e2 = (const int*)d_in[30];
    }

    // stage 1: 125-tap conv (1->32) + relu, into X
    conv1_kernel<<<(N1C + 255) / 256, 256>>>(feats, nbr1, W1, pX, N1C, N0C, 125);

    // two residual blocks at level 1 (32 ch), X updated in place
    run_block32(blk[0], nbr_e1, pX, pT0, pT1);
    run_block32(blk[1], nbr_e1, pX, pT0, pT1);

    // downsample conv (32->64), no BN/relu, into T1
    conv_kernel<32, 64, 128><<<(N2C + 127) / 128, 256>>>(pX, nbr2, W2, pT1, N2C, N1C, 27);

    // two residual blocks at level 2 (64 ch); final one writes d_out
    run_block64(blk[2], nbr_e2, pT1, pT0, pX, pT1);
    run_block64(blk[3], nbr_e2, pT1, pT0, pX, (float*)d_out);
}

// round 5
// speedup vs baseline: 1.0342x; 1.0342x over previous
#include <cuda_runtime.h>
#include <math.h>

#define N0C 200000
#define N1C 160000
#define N2C 100000

// ---------------- scratch (static device arrays; no allocation) -------------
__device__ __align__(16) float g_X [N2C * 64];   // 6.4M floats (covers N1*32 too)
__device__ __align__(16) float g_T0[N2C * 64];
__device__ __align__(16) float g_T1[N2C * 64];
__device__ double g_part[2 * 256 * 64];          // BN partials: [sum | sumsq]
__device__ float  g_scale[64];
__device__ float  g_shift[64];

// packed fp32x2 FMA (Blackwell sm_100+): d = a*b + d, lanewise IEEE fp32
#define FMA2(d, a, b) \
    asm("fma.rn.f32x2 %0, %1, %2, %0;" : "+l"(d) : "l"(a), "l"(b))

__device__ __forceinline__ unsigned long long pack_dup(float v) {
    unsigned int vi = __float_as_uint(v);
    unsigned long long r;
    asm("mov.b64 %0, {%1, %1};" : "=l"(r) : "r"(vi));
    return r;
}

// ---------------- conv1: 125 taps, Cin=1 -> Cout=32, fused relu -------------
__global__ __launch_bounds__(256) void conv1_kernel(
    const float* __restrict__ feats, const int* __restrict__ nbr,
    const float* __restrict__ W, float* __restrict__ out,
    int Nout, int Nin, int taps)
{
    __shared__ ulonglong2 Ws[125 * 8];   // (taps, 32 floats) = 8 ulonglong2/tap
    const ulonglong2* Wg = reinterpret_cast<const ulonglong2*>(W);
    for (int i = threadIdx.x; i < taps * 8; i += 256)
        Ws[i] = Wg[i];
    __syncthreads();

    int j = blockIdx.x * 256 + threadIdx.x;
    if (j >= Nout) return;

    unsigned long long acc[16];
#pragma unroll
    for (int c = 0; c < 16; c++) acc[c] = 0ull;

    for (int k = 0; k < taps; k++) {
        int idx = nbr[k * Nout + j];
        if (idx < Nin) {
            unsigned long long vp = pack_dup(feats[idx]);
#pragma unroll
            for (int m = 0; m < 8; m++) {
                ulonglong2 w = Ws[k * 8 + m];
                FMA2(acc[2 * m + 0], vp, w.x);
                FMA2(acc[2 * m + 1], vp, w.y);
            }
        }
    }
    float4* o = reinterpret_cast<float4*>(out + (size_t)j * 32);
#pragma unroll
    for (int m = 0; m < 8; m++) {
        float2 lo = *reinterpret_cast<float2*>(&acc[2 * m + 0]);
        float2 hi = *reinterpret_cast<float2*>(&acc[2 * m + 1]);
        o[m] = make_float4(fmaxf(lo.x, 0.f), fmaxf(lo.y, 0.f),
                           fmaxf(hi.x, 0.f), fmaxf(hi.y, 0.f));
    }
}

// ---------------- generic tiled gather-GEMM conv (f32x2 packed) -------------
// out[j, :] = sum_k X[nbr[k, j], :] @ W[k]   (nbr==Nin -> zero row)
// TM output rows per block, 256 threads, STATIC shared memory only.
// A-tile staged TRANSPOSED as plain float: AsT[kk][row]; the f32x2 broadcast
// operand {v,v} is built in registers (LDS.32 + MOV).
// Thread (tcol = tid&7, trow = tid>>3) computes RPT rows x CPT cols.
template <int CIN, int COUT, int TM>
__global__ __launch_bounds__(256) void conv2_kernel(
    const float* __restrict__ X, const int* __restrict__ nbr,
    const float* __restrict__ W, float* __restrict__ out,
    int Nout, int Nin, int taps)
{
    constexpr int TMP = TM + 1;         // padded row stride (reduces store conflicts)
    constexpr int CPT = COUT / 8;       // cols per thread: 4 or 8
    constexpr int RPT = TM / 32;        // rows per thread: 4 (TM=128) or 2 (TM=64)
    constexpr int QPR = CIN / 4;        // float4 per gathered row
    constexpr int STAGE_IT = TM * QPR / 256;
    constexpr int WIT = (CIN * COUT) / 1024;  // W float4 loads per thread

    __shared__ float AsT[CIN * TMP];
    __shared__ float Ws[CIN * COUT];

    const int tid  = threadIdx.x;
    const int tcol = tid & 7;
    const int trow = tid >> 3;          // 0..31
    const int row0 = blockIdx.x * TM;

    unsigned long long acc[RPT][CPT / 2];
#pragma unroll
    for (int i = 0; i < RPT; i++)
#pragma unroll
        for (int j = 0; j < CPT / 2; j++) acc[i][j] = 0ull;

    for (int k = 0; k < taps; k++) {
        // stage weights for this tap
        const float4* Wk4 = reinterpret_cast<const float4*>(W + (size_t)k * CIN * COUT);
#pragma unroll
        for (int i = 0; i < WIT; i++)
            reinterpret_cast<float4*>(Ws)[tid + 256 * i] = Wk4[tid + 256 * i];

        // stage gathered A tile, transposed
#pragma unroll
        for (int it = 0; it < STAGE_IT; it++) {
            int Q = tid + 256 * it;
            int r = Q / QPR;
            int q = Q - r * QPR;
            int grow = row0 + r;
            float4 v = make_float4(0.f, 0.f, 0.f, 0.f);
            if (grow < Nout) {
                int idx = nbr[k * Nout + grow];
                if (idx < Nin)
                    v = reinterpret_cast<const float4*>(X + (size_t)idx * CIN)[q];
            }
            AsT[(4 * q + 0) * TMP + r] = v.x;
            AsT[(4 * q + 1) * TMP + r] = v.y;
            AsT[(4 * q + 2) * TMP + r] = v.z;
            AsT[(4 * q + 3) * TMP + r] = v.w;
        }
        __syncthreads();

        // register-tiled accumulate, packed f32x2
#pragma unroll 4
        for (int kk = 0; kk < CIN; kk++) {
            unsigned long long a[RPT];
#pragma unroll
            for (int i = 0; i < RPT; i++)
                a[i] = pack_dup(AsT[kk * TMP + trow * RPT + i]);
            const ulonglong2* wrow = reinterpret_cast<const ulonglong2*>(Ws + kk * COUT);
#pragma unroll
            for (int j = 0; j < CPT / 4; j++) {
                ulonglong2 w = wrow[tcol * (CPT / 4) + j];
#pragma unroll
                for (int i = 0; i < RPT; i++) {
                    FMA2(acc[i][2 * j + 0], a[i], w.x);
                    FMA2(acc[i][2 * j + 1], a[i], w.y);
                }
            }
        }
        __syncthreads();
    }

    // store raw conv output (BN applied later)
#pragma unroll
    for (int i = 0; i < RPT; i++) {
        int grow = row0 + trow * RPT + i;
        if (grow < Nout) {
            float4* o = reinterpret_cast<float4*>(out + (size_t)grow * COUT);
#pragma unroll
            for (int j = 0; j < CPT / 4; j++) {
                float2 lo = *reinterpret_cast<float2*>(&acc[i][2 * j + 0]);
                float2 hi = *reinterpret_cast<float2*>(&acc[i][2 * j + 1]);
                o[tcol * (CPT / 4) + j] = make_float4(lo.x, lo.y, hi.x, hi.y);
            }
        }
    }
}

// ---------------- BN statistics: deterministic two-stage reduction ----------
template <int C>
__global__ __launch_bounds__(256) void reduce_kernel(const float* __restrict__ x, int N)
{
    constexpr int G = 256 / C;
    int c = threadIdx.x % C;
    int g = threadIdx.x / C;
    double s = 0.0, ss = 0.0;
    for (long r = (long)blockIdx.x * G + g; r < N; r += (long)gridDim.x * G) {
        double v = (double)x[r * C + c];
        s += v;
        ss += v * v;
    }
    __shared__ double sh[512];
    sh[threadIdx.x] = s;
    sh[256 + threadIdx.x] = ss;
    __syncthreads();
    if (g == 0) {
#pragma unroll
        for (int gg = 1; gg < G; gg++) {
            s  += sh[gg * C + c];
            ss += sh[256 + gg * C + c];
        }
        g_part[blockIdx.x * 64 + c] = s;
        g_part[16384 + blockIdx.x * 64 + c] = ss;
    }
}

// parallel finalize: 256 threads, G=256/C partial-groups per channel
template <int C>
__global__ __launch_bounds__(256) void finalize_kernel(
    const float* __restrict__ gam, const float* __restrict__ bet, double Ninv)
{
    constexpr int G = 256 / C;
    int c = threadIdx.x % C;
    int g = threadIdx.x / C;
    double s = 0.0, ss = 0.0;
    for (int p = g; p < 256; p += G) {
        s  += g_part[p * 64 + c];
        ss += g_part[16384 + p * 64 + c];
    }
    __shared__ double sh[512];
    sh[threadIdx.x] = s;
    sh[256 + threadIdx.x] = ss;
    __syncthreads();
    if (g == 0) {
#pragma unroll
        for (int gg = 1; gg < G; gg++) {
            s  += sh[gg * C + c];
            ss += sh[256 + gg * C + c];
        }
        double mu  = s * Ninv;
        double var = ss * Ninv - mu * mu;
        float  sc  = (float)((double)gam[c] / sqrt(var + 1e-5));
        g_scale[c] = sc;
        g_shift[c] = bet[c] - (float)mu * sc;
    }
}

// ---------------- elementwise BN apply ---------------------------------------
__global__ void ew_bn_relu_kernel(const float* __restrict__ x, float* __restrict__ y,
                                  int total, int cmask)
{
    int i = blockIdx.x * blockDim.x + threadIdx.x;
    if (i < total) {
        int c = i & cmask;
        y[i] = fmaxf(fmaf(x[i], g_scale[c], g_shift[c]), 0.f);
    }
}

__global__ void ew_bn_add_relu_kernel(const float* __restrict__ x,
                                      const float* __restrict__ res,
                                      float* __restrict__ y, int total, int cmask)
{
    int i = blockIdx.x * blockDim.x + threadIdx.x;
    if (i < total) {
        int c = i & cmask;
        y[i] = fmaxf(res[i] + fmaf(x[i], g_scale[c], g_shift[c]), 0.f);
    }
}

// ---------------- host orchestration -----------------------------------------
static void run_block32(const float* const* p, const int* nbr,
                        float* x, float* t0, float* t1)
{
    int tiles = (N1C + 127) / 128;
    int tot   = N1C * 32;
    conv2_kernel<32, 32, 128><<<tiles, 256>>>(x, nbr, p[0], t0, N1C, N1C, 27);
    reduce_kernel<32><<<256, 256>>>(t0, N1C);
    finalize_kernel<32><<<1, 256>>>(p[2], p[3], 1.0 / N1C);
    ew_bn_relu_kernel<<<(tot + 255) / 256, 256>>>(t0, t1, tot, 31);
    conv2_kernel<32, 32, 128><<<tiles, 256>>>(t1, nbr, p[1], t0, N1C, N1C, 27);
    reduce_kernel<32><<<256, 256>>>(t0, N1C);
    finalize_kernel<32><<<1, 256>>>(p[4], p[5], 1.0 / N1C);
    ew_bn_add_relu_kernel<<<(tot + 255) / 256, 256>>>(t0, x, x, tot, 31);
}

static void run_block64(const float* const* p, const int* nbr,
                        float* x, float* t0, float* scratch, float* dst)
{
    int tiles = (N2C + 63) / 64;
    int tot   = N2C * 64;
    conv2_kernel<64, 64, 64><<<tiles, 256>>>(x, nbr, p[0], t0, N2C, N2C, 27);
    reduce_kernel<64><<<256, 256>>>(t0, N2C);
    finalize_kernel<64><<<1, 256>>>(p[2], p[3], 1.0 / N2C);
    ew_bn_relu_kernel<<<(tot + 255) / 256, 256>>>(t0, scratch, tot, 63);
    conv2_kernel<64, 64, 64><<<tiles, 256>>>(scratch, nbr, p[1], t0, N2C, N2C, 27);
    reduce_kernel<64><<<256, 256>>>(t0, N2C);
    finalize_kernel<64><<<1, 256>>>(p[4], p[5], 1.0 / N2C);
    ew_bn_add_relu_kernel<<<(tot + 255) / 256, 256>>>(t0, x, dst, tot, 63);
}

extern "C" void kernel_launch(void* const* d_in, const int* in_sizes, int n_in,
                              void* d_out, int out_size)
{
    // fully stateless: no static guards, no attributes, static smem only
    float* pX;  float* pT0;  float* pT1;
    cudaGetSymbolAddress((void**)&pX,  g_X);
    cudaGetSymbolAddress((void**)&pT0, g_T0);
    cudaGetSymbolAddress((void**)&pT1, g_T1);

    const float* feats = (const float*)d_in[0];
    const float* W1    = (const float*)d_in[1];
    const float* W2    = (const float*)d_in[2];

    const int *nbr1, *nbr_e1, *nbr2, *nbr_e2;
    const float* blk[4][6];  // per block: wa, wb, g1, b1, g2, b2

    if (in_sizes[3] == 125 * N1C) {
        // dict insertion order: feats, W1, W2, nbr1, nbr_e1, nbr2, nbr_e2, blocks...
        nbr1   = (const int*)d_in[3];
        nbr_e1 = (const int*)d_in[4];
        nbr2   = (const int*)d_in[5];
        nbr_e2 = (const int*)d_in[6];
        for (int b = 0; b < 4; b++)
            for (int j = 0; j < 6; j++)
                blk[b][j] = (const float*)d_in[7 + b * 6 + j];
    } else {
        // reference signature order: feats, W1, W2, blocks..., nbr1, nbr_e1, nbr2, nbr_e2
        for (int b = 0; b < 4; b++)
            for (int j = 0; j < 6; j++)
                blk[b][j] = (const float*)d_in[3 + b * 6 + j];
        nbr1   = (const int*)d_in[27];
        nbr_e1 = (const int*)d_in[28];
        nbr2   = (const int*)d_in[29];
        nbr_e2 = (const int*)d_in[30];
    }

    // stage 1: 125-tap conv (1->32) + relu, into X
    conv1_kernel<<<(N1C + 255) / 256, 256>>>(feats, nbr1, W1, pX, N1C, N0C, 125);

    // two residual blocks at level 1 (32 ch), X updated in place
    run_block32(blk[0], nbr_e1, pX, pT0, pT1);
    run_block32(blk[1], nbr_e1, pX, pT0, pT1);

    // downsample conv (32->64), no BN/relu, into T1
    conv2_kernel<32, 64, 128><<<(N2C + 127) / 128, 256>>>(pX, nbr2, W2, pT1, N2C, N1C, 27);

    // two residual blocks at level 2 (64 ch); final one writes d_out
    run_block64(blk[2], nbr_e2, pT1, pT0, pX, pT1);
    run_block64(blk[3], nbr_e2, pT1, pT0, pX, (float*)d_out);
}